// round 5
// baseline (speedup 1.0000x reference)
#include <cuda_runtime.h>
#include <cstdint>

#define N_NODES  100000
#define N_EDGES  1600000
#define CH       128
#define N_GRAPHS 256

// ---------------- scratch (device globals; no allocation allowed) ----------
__device__ float g_bufH[(size_t)N_NODES * CH];   // h (GEMM output, gather source)
__device__ float g_bufA[(size_t)N_NODES * CH];   // agg (scatter dest / next GEMM input)
__device__ int   g_degcnt[N_NODES];
__device__ float g_dinv[N_NODES];                // 1/deg
__device__ float g_dis[N_NODES];                 // deg^-0.5
__device__ float g_psum[N_GRAPHS];
__device__ float g_cnt[N_GRAPHS];

// ---------------- small setup kernels --------------------------------------
__global__ void k_zero() {
    int i = blockIdx.x * blockDim.x + threadIdx.x;
    if (i < N_NODES) g_degcnt[i] = 0;
    if (i < N_GRAPHS) { g_psum[i] = 0.f; g_cnt[i] = 0.f; }
}

__global__ void k_degcount(const int* __restrict__ dst) {
    int e = blockIdx.x * blockDim.x + threadIdx.x;
    if (e < N_EDGES) atomicAdd(&g_degcnt[dst[e]], 1);
}

__global__ void k_degfin() {
    int i = blockIdx.x * blockDim.x + threadIdx.x;
    if (i < N_NODES) {
        float deg = 1.f + (float)g_degcnt[i];
        g_dinv[i] = 1.f / deg;
        g_dis[i]  = rsqrtf(deg);
    }
}

// ---------------- tiled SGEMM: [M,128] @ [128,128] --------------------------
// Block: 256 threads computes 64 rows x 128 cols (8x4 per-thread register tile).
// A source: external X (layer 1) or g_bufA (layer 2), selected by template flag
// so NO device-symbol address ever crosses the host/device boundary.
// Epilogue writes H = A@W -> g_bufH and AggInit = H * dinv[row] -> g_bufA.
// RELU_BIAS fuses the previous layer's relu(a + b1[k]) into the A-tile load.
template<bool RELU_BIAS, bool X_FROM_AGG>
__global__ void __launch_bounds__(256)
k_gemm(const float* __restrict__ Xext, const float* __restrict__ W,
       const float* __restrict__ bias)
{
    __shared__ float  As[64][16];
    __shared__ float4 Ws[16][32];

    const float* __restrict__ X = X_FROM_AGG ? (const float*)g_bufA : Xext;

    const int tx    = threadIdx.x;
    const int row0  = blockIdx.x * 64;
    const int lane  = tx & 31;      // output col group (4 cols)
    const int rgrp  = tx >> 5;      // output row group (8 rows)
    const int lrow  = tx >> 2;      // A-load row   0..63
    const int lk4   = (tx & 3) * 4; // A-load k off 0,4,8,12

    float acc[8][4];
    #pragma unroll
    for (int i = 0; i < 8; i++)
        #pragma unroll
        for (int j = 0; j < 4; j++) acc[i][j] = 0.f;

    for (int kt = 0; kt < CH; kt += 16) {
        // load A tile 64x16
        float4 av = make_float4(0.f, 0.f, 0.f, 0.f);
        int grow = row0 + lrow;
        if (grow < N_NODES) {
            av = *(const float4*)(X + (size_t)grow * CH + kt + lk4);
            if (RELU_BIAS) {
                av.x = fmaxf(av.x + bias[kt + lk4 + 0], 0.f);
                av.y = fmaxf(av.y + bias[kt + lk4 + 1], 0.f);
                av.z = fmaxf(av.z + bias[kt + lk4 + 2], 0.f);
                av.w = fmaxf(av.w + bias[kt + lk4 + 3], 0.f);
            }
        }
        *(float4*)&As[lrow][lk4] = av;

        // load W tile 16x128 (512 float4 / 256 threads)
        #pragma unroll
        for (int i = 0; i < 2; i++) {
            int idx = tx + i * 256;
            int kk = idx >> 5, c4 = idx & 31;
            Ws[kk][c4] = ((const float4*)W)[(size_t)(kt + kk) * 32 + c4];
        }
        __syncthreads();

        #pragma unroll
        for (int kk = 0; kk < 16; kk++) {
            float4 w = Ws[kk][lane];
            #pragma unroll
            for (int i = 0; i < 8; i++) {
                float a = As[rgrp * 8 + i][kk];   // smem broadcast
                acc[i][0] += a * w.x;
                acc[i][1] += a * w.y;
                acc[i][2] += a * w.z;
                acc[i][3] += a * w.w;
            }
        }
        __syncthreads();
    }

    #pragma unroll
    for (int i = 0; i < 8; i++) {
        int r = row0 + rgrp * 8 + i;
        if (r < N_NODES) {
            float4 v = make_float4(acc[i][0], acc[i][1], acc[i][2], acc[i][3]);
            *(float4*)(g_bufH + (size_t)r * CH + lane * 4) = v;
            float di = g_dinv[r];
            float4 u = make_float4(v.x * di, v.y * di, v.z * di, v.w * di);
            *(float4*)(g_bufA + (size_t)r * CH + lane * 4) = u;
        }
    }
}

// ---------------- edge scatter: Agg[dst] += H[src] * dis[src]*dis[dst] ------
// One warp per edge. Lane 0 loads indices + coefficient, broadcast via shfl;
// each lane then does one float4 gather + one red.global.add.v4.
__global__ void __launch_bounds__(256)
k_scatter(const int* __restrict__ src, const int* __restrict__ dst)
{
    int gtid = blockIdx.x * blockDim.x + threadIdx.x;
    int e = gtid >> 5;
    if (e >= N_EDGES) return;
    int lane = gtid & 31;

    int s = 0, d = 0;
    float coef = 0.f;
    if (lane == 0) {
        s = __ldg(src + e);
        d = __ldg(dst + e);
        coef = g_dis[s] * g_dis[d];
    }
    s    = __shfl_sync(0xFFFFFFFFu, s, 0);
    d    = __shfl_sync(0xFFFFFFFFu, d, 0);
    coef = __shfl_sync(0xFFFFFFFFu, coef, 0);

    float4 v = *(const float4*)(g_bufH + (size_t)s * CH + lane * 4);
    v.x *= coef; v.y *= coef; v.z *= coef; v.w *= coef;
    float* p = g_bufA + (size_t)d * CH + lane * 4;
    asm volatile("red.global.add.v4.f32 [%0], {%1,%2,%3,%4};"
                 :: "l"(p), "f"(v.x), "f"(v.y), "f"(v.z), "f"(v.w)
                 : "memory");
}

// ---------------- fused relu(+b2) + FC dot + segment mean accumulation ------
__global__ void __launch_bounds__(256)
k_pool(const float* __restrict__ b2,
       const float* __restrict__ Wfc, const int* __restrict__ batch)
{
    int gtid = blockIdx.x * blockDim.x + threadIdx.x;
    int n = gtid >> 5;
    if (n >= N_NODES) return;
    int lane = gtid & 31;
    float4 h = *(const float4*)(g_bufA + (size_t)n * CH + lane * 4);
    float4 bb = ((const float4*)b2)[lane];
    float4 w  = ((const float4*)Wfc)[lane];
    float s = fmaxf(h.x + bb.x, 0.f) * w.x
            + fmaxf(h.y + bb.y, 0.f) * w.y
            + fmaxf(h.z + bb.z, 0.f) * w.z
            + fmaxf(h.w + bb.w, 0.f) * w.w;
    #pragma unroll
    for (int off = 16; off; off >>= 1)
        s += __shfl_xor_sync(0xFFFFFFFFu, s, off);
    if (lane == 0) {
        int g = __ldg(batch + n);
        atomicAdd(&g_psum[g], s);
        atomicAdd(&g_cnt[g], 1.f);
    }
}

__global__ void k_final(float* __restrict__ out, const float* __restrict__ bfc) {
    int g = threadIdx.x;
    if (g < N_GRAPHS) out[g] = g_psum[g] / fmaxf(g_cnt[g], 1.f) + bfc[0];
}

// ---------------- launch -----------------------------------------------------
extern "C" void kernel_launch(void* const* d_in, const int* in_sizes, int n_in,
                              void* d_out, int out_size)
{
    (void)in_sizes; (void)n_in; (void)out_size;
    const float* x     = (const float*)d_in[0];
    const int*   ei    = (const int*)d_in[1];   // [2, E] row-major
    const int*   batch = (const int*)d_in[2];
    const float* W1    = (const float*)d_in[3];
    const float* b1    = (const float*)d_in[4];
    const float* W2    = (const float*)d_in[5];
    const float* b2    = (const float*)d_in[6];
    const float* Wfc   = (const float*)d_in[7];
    const float* bfc   = (const float*)d_in[8];
    float* out = (float*)d_out;

    const int* src = ei;            // edge_index[0]
    const int* dst = ei + N_EDGES;  // edge_index[1]

    // degree + zeroing
    k_zero<<<(N_NODES + 255) / 256, 256>>>();
    k_degcount<<<(N_EDGES + 255) / 256, 256>>>(dst);
    k_degfin<<<(N_NODES + 255) / 256, 256>>>();

    const int gemm_grid    = (N_NODES + 63) / 64;
    const int scatter_grid = (N_EDGES * 32 + 255) / 256;
    const int pool_grid    = (N_NODES * 32 + 255) / 256;

    // Layer 1: h1 = x@W1 -> g_bufH ; agg1-init = h1/deg -> g_bufA ; scatter edges
    k_gemm<false, false><<<gemm_grid, 256>>>(x, W1, nullptr);
    k_scatter<<<scatter_grid, 256>>>(src, dst);

    // Layer 2: A = relu(agg1 + b1) fused into A-load, read from g_bufA in-place
    k_gemm<true, true><<<gemm_grid, 256>>>(nullptr, W2, b1);
    k_scatter<<<scatter_grid, 256>>>(src, dst);

    // relu(agg2+b2), FC dot, segment mean
    k_pool<<<pool_grid, 256>>>(b2, Wfc, batch);
    k_final<<<1, 256>>>(out, bfc);
}

// round 9
// speedup vs baseline: 1.5030x; 1.5030x over previous
#include <cuda_runtime.h>
#include <cstdint>

#define N_NODES  100000
#define N_EDGES  1600000
#define CH       128
#define N_GRAPHS 256

#define SCAN_BLK 512
#define N_SCAN_BLKS ((N_NODES + SCAN_BLK - 1) / SCAN_BLK)   // 196

// ---------------- scratch (device globals; no allocation allowed) ----------
__device__ float g_bufH[(size_t)N_NODES * CH];   // h (GEMM output, gather source)
__device__ float g_bufA[(size_t)N_NODES * CH];   // agg (gather output / next GEMM input)
__device__ int   g_degcnt[N_NODES];              // in-degree (no self loop)
__device__ int   g_rowstart[N_NODES];            // CSR row starts (exclusive scan of degcnt)
__device__ int   g_rowcur[N_NODES];              // placement cursors
__device__ int   g_blksum[N_SCAN_BLKS];          // scan block sums
__device__ int2  g_edge[N_EDGES];                // CSR: {src, coef-as-int-bits} per dst-sorted edge
__device__ float g_dinv[N_NODES];                // 1/deg
__device__ float g_dis[N_NODES];                 // deg^-0.5
__device__ float g_psum[N_GRAPHS];
__device__ float g_cnt[N_GRAPHS];

// ---------------- setup -----------------------------------------------------
__global__ void k_zero() {
    int i = blockIdx.x * blockDim.x + threadIdx.x;
    if (i < N_NODES) { g_degcnt[i] = 0; g_rowcur[i] = 0; }
    if (i < N_GRAPHS) { g_psum[i] = 0.f; g_cnt[i] = 0.f; }
}

__global__ void k_degcount(const int* __restrict__ dst) {
    int e = blockIdx.x * blockDim.x + threadIdx.x;
    if (e < N_EDGES) atomicAdd(&g_degcnt[dst[e]], 1);
}

__global__ void k_degfin() {
    int i = blockIdx.x * blockDim.x + threadIdx.x;
    if (i < N_NODES) {
        float deg = 1.f + (float)g_degcnt[i];
        g_dinv[i] = 1.f / deg;
        g_dis[i]  = rsqrtf(deg);
    }
}

// ---------------- CSR build: 3-pass exclusive scan + placement fill ---------
__global__ void __launch_bounds__(SCAN_BLK) k_scan1() {
    __shared__ int sc[SCAN_BLK];
    int t = threadIdx.x;
    int i = blockIdx.x * SCAN_BLK + t;
    int v = (i < N_NODES) ? g_degcnt[i] : 0;
    sc[t] = v;
    __syncthreads();
    #pragma unroll
    for (int o = 1; o < SCAN_BLK; o <<= 1) {
        int u = (t >= o) ? sc[t - o] : 0;
        __syncthreads();
        sc[t] += u;
        __syncthreads();
    }
    if (i < N_NODES) g_rowstart[i] = sc[t] - v;      // exclusive within block
    if (t == SCAN_BLK - 1) g_blksum[blockIdx.x] = sc[t];
}

__global__ void __launch_bounds__(256) k_scan2() {
    __shared__ int sc[256];
    int t = threadIdx.x;
    int v = (t < N_SCAN_BLKS) ? g_blksum[t] : 0;
    sc[t] = v;
    __syncthreads();
    #pragma unroll
    for (int o = 1; o < 256; o <<= 1) {
        int u = (t >= o) ? sc[t - o] : 0;
        __syncthreads();
        sc[t] += u;
        __syncthreads();
    }
    if (t < N_SCAN_BLKS) g_blksum[t] = sc[t] - v;    // exclusive block offsets
}

__global__ void k_scan3() {
    int i = blockIdx.x * blockDim.x + threadIdx.x;
    if (i < N_NODES) g_rowstart[i] += g_blksum[i / SCAN_BLK];
}

__global__ void __launch_bounds__(256)
k_fill(const int* __restrict__ src, const int* __restrict__ dst) {
    int e = blockIdx.x * blockDim.x + threadIdx.x;
    if (e >= N_EDGES) return;
    int s = __ldg(src + e);
    int d = __ldg(dst + e);
    int pos = g_rowstart[d] + atomicAdd(&g_rowcur[d], 1);
    float coef = g_dis[s] * g_dis[d];
    g_edge[pos] = make_int2(s, __float_as_int(coef));
}

// ---------------- tiled SGEMM: [M,128] @ [128,128], 128x128 block tile ------
// 256 threads, 8x8 per-thread micro-tile, A transposed in smem.
// Per kk-step: 4 LDS.128 feed 64 FMA. Epilogue writes H only.
template<bool RELU_BIAS, bool X_FROM_AGG>
__global__ void __launch_bounds__(256)
k_gemm(const float* __restrict__ Xext, const float* __restrict__ W,
       const float* __restrict__ bias)
{
    __shared__ float As[16][132];   // [k][m], padded
    __shared__ float Ws[16][128];   // [k][n]

    const float* __restrict__ X = X_FROM_AGG ? (const float*)g_bufA : Xext;

    const int tx   = threadIdx.x;
    const int row0 = blockIdx.x * 128;
    const int lrow = tx >> 2;          // A-load row 0..63 (and +64)
    const int lk4  = (tx & 3) * 4;     // A-load k offset 0,4,8,12
    const int cx   = tx & 15;          // col block: cols cx*8 .. cx*8+7
    const int ry   = tx >> 4;          // row block: rows ry*8 .. ry*8+7

    float acc[8][8];
    #pragma unroll
    for (int i = 0; i < 8; i++)
        #pragma unroll
        for (int j = 0; j < 8; j++) acc[i][j] = 0.f;

    for (int kt = 0; kt < CH; kt += 16) {
        // A tile: 128 rows x 16 k, transposed store
        #pragma unroll
        for (int h = 0; h < 2; h++) {
            int r = row0 + lrow + h * 64;
            float4 av = make_float4(0.f, 0.f, 0.f, 0.f);
            if (r < N_NODES) {
                av = *(const float4*)(X + (size_t)r * CH + kt + lk4);
                if (RELU_BIAS) {
                    av.x = fmaxf(av.x + bias[kt + lk4 + 0], 0.f);
                    av.y = fmaxf(av.y + bias[kt + lk4 + 1], 0.f);
                    av.z = fmaxf(av.z + bias[kt + lk4 + 2], 0.f);
                    av.w = fmaxf(av.w + bias[kt + lk4 + 3], 0.f);
                }
            }
            As[lk4 + 0][lrow + h * 64] = av.x;
            As[lk4 + 1][lrow + h * 64] = av.y;
            As[lk4 + 2][lrow + h * 64] = av.z;
            As[lk4 + 3][lrow + h * 64] = av.w;
        }
        // W tile: 16 x 128 (512 float4 / 256 threads)
        #pragma unroll
        for (int h = 0; h < 2; h++) {
            int idx = tx + h * 256;
            int kk = idx >> 5, c4 = idx & 31;
            *(float4*)&Ws[kk][c4 * 4] = ((const float4*)W)[(size_t)(kt + kk) * 32 + c4];
        }
        __syncthreads();

        #pragma unroll
        for (int kk = 0; kk < 16; kk++) {
            float a[8], b[8];
            *(float4*)&a[0] = *(const float4*)&As[kk][ry * 8];
            *(float4*)&a[4] = *(const float4*)&As[kk][ry * 8 + 4];
            *(float4*)&b[0] = *(const float4*)&Ws[kk][cx * 8];
            *(float4*)&b[4] = *(const float4*)&Ws[kk][cx * 8 + 4];
            #pragma unroll
            for (int i = 0; i < 8; i++)
                #pragma unroll
                for (int j = 0; j < 8; j++)
                    acc[i][j] = fmaf(a[i], b[j], acc[i][j]);
        }
        __syncthreads();
    }

    #pragma unroll
    for (int i = 0; i < 8; i++) {
        int r = row0 + ry * 8 + i;
        if (r < N_NODES) {
            *(float4*)(g_bufH + (size_t)r * CH + cx * 8) =
                make_float4(acc[i][0], acc[i][1], acc[i][2], acc[i][3]);
            *(float4*)(g_bufH + (size_t)r * CH + cx * 8 + 4) =
                make_float4(acc[i][4], acc[i][5], acc[i][6], acc[i][7]);
        }
    }
}

// ---------------- CSR gather: Agg[n] = H[n]/deg + sum_e coef*H[src] ---------
// Warp per node; register accumulation; one plain store. NO atomics.
// Edge stream is packed {src, coef} int2: one 8B load per edge per lane.
__global__ void __launch_bounds__(256)
k_gather()
{
    int gt = blockIdx.x * blockDim.x + threadIdx.x;
    int n = gt >> 5;
    if (n >= N_NODES) return;
    int lane = gt & 31;

    int beg = g_rowstart[n];
    int cnt = g_degcnt[n];
    float di = g_dinv[n];

    float4 h = *(const float4*)(g_bufH + (size_t)n * CH + lane * 4);
    float4 acc = make_float4(h.x * di, h.y * di, h.z * di, h.w * di);

    for (int base = 0; base < cnt; base += 32) {
        int rem = cnt - base;
        int m = rem < 32 ? rem : 32;
        int2 ec = make_int2(0, 0);
        if (lane < m) ec = __ldg(g_edge + beg + base + lane);
        int j = 0;
        for (; j + 2 <= m; j += 2) {
            int   s0 = __shfl_sync(0xFFFFFFFFu, ec.x, j);
            int   s1 = __shfl_sync(0xFFFFFFFFu, ec.x, j + 1);
            float c0 = __int_as_float(__shfl_sync(0xFFFFFFFFu, ec.y, j));
            float c1 = __int_as_float(__shfl_sync(0xFFFFFFFFu, ec.y, j + 1));
            float4 v0 = *(const float4*)(g_bufH + (size_t)s0 * CH + lane * 4);
            float4 v1 = *(const float4*)(g_bufH + (size_t)s1 * CH + lane * 4);
            acc.x = fmaf(c0, v0.x, fmaf(c1, v1.x, acc.x));
            acc.y = fmaf(c0, v0.y, fmaf(c1, v1.y, acc.y));
            acc.z = fmaf(c0, v0.z, fmaf(c1, v1.z, acc.z));
            acc.w = fmaf(c0, v0.w, fmaf(c1, v1.w, acc.w));
        }
        if (j < m) {
            int   s0 = __shfl_sync(0xFFFFFFFFu, ec.x, j);
            float c0 = __int_as_float(__shfl_sync(0xFFFFFFFFu, ec.y, j));
            float4 v0 = *(const float4*)(g_bufH + (size_t)s0 * CH + lane * 4);
            acc.x = fmaf(c0, v0.x, acc.x);
            acc.y = fmaf(c0, v0.y, acc.y);
            acc.z = fmaf(c0, v0.z, acc.z);
            acc.w = fmaf(c0, v0.w, acc.w);
        }
    }

    *(float4*)(g_bufA + (size_t)n * CH + lane * 4) = acc;
}

// ---------------- fused relu(+b2) + FC dot + segment mean accumulation ------
__global__ void __launch_bounds__(256)
k_pool(const float* __restrict__ b2,
       const float* __restrict__ Wfc, const int* __restrict__ batch)
{
    int gtid = blockIdx.x * blockDim.x + threadIdx.x;
    int n = gtid >> 5;
    if (n >= N_NODES) return;
    int lane = gtid & 31;
    float4 h = *(const float4*)(g_bufA + (size_t)n * CH + lane * 4);
    float4 bb = ((const float4*)b2)[lane];
    float4 w  = ((const float4*)Wfc)[lane];
    float s = fmaxf(h.x + bb.x, 0.f) * w.x
            + fmaxf(h.y + bb.y, 0.f) * w.y
            + fmaxf(h.z + bb.z, 0.f) * w.z
            + fmaxf(h.w + bb.w, 0.f) * w.w;
    #pragma unroll
    for (int off = 16; off; off >>= 1)
        s += __shfl_xor_sync(0xFFFFFFFFu, s, off);
    if (lane == 0) {
        int g = __ldg(batch + n);
        atomicAdd(&g_psum[g], s);
        atomicAdd(&g_cnt[g], 1.f);
    }
}

__global__ void k_final(float* __restrict__ out, const float* __restrict__ bfc) {
    int g = threadIdx.x;
    if (g < N_GRAPHS) out[g] = g_psum[g] / fmaxf(g_cnt[g], 1.f) + bfc[0];
}

// ---------------- launch -----------------------------------------------------
extern "C" void kernel_launch(void* const* d_in, const int* in_sizes, int n_in,
                              void* d_out, int out_size)
{
    (void)in_sizes; (void)n_in; (void)out_size;
    const float* x     = (const float*)d_in[0];
    const int*   ei    = (const int*)d_in[1];   // [2, E] row-major
    const int*   batch = (const int*)d_in[2];
    const float* W1    = (const float*)d_in[3];
    const float* b1    = (const float*)d_in[4];
    const float* W2    = (const float*)d_in[5];
    const float* b2    = (const float*)d_in[6];
    const float* Wfc   = (const float*)d_in[7];
    const float* bfc   = (const float*)d_in[8];
    float* out = (float*)d_out;

    const int* src = ei;            // edge_index[0]
    const int* dst = ei + N_EDGES;  // edge_index[1]

    // degree + CSR build
    k_zero<<<(N_NODES + 255) / 256, 256>>>();
    k_degcount<<<(N_EDGES + 255) / 256, 256>>>(dst);
    k_degfin<<<(N_NODES + 255) / 256, 256>>>();
    k_scan1<<<N_SCAN_BLKS, SCAN_BLK>>>();
    k_scan2<<<1, 256>>>();
    k_scan3<<<(N_NODES + 255) / 256, 256>>>();
    k_fill<<<(N_EDGES + 255) / 256, 256>>>(src, dst);

    const int gemm_grid   = (N_NODES + 127) / 128;
    const int gather_grid = (N_NODES * 32 + 255) / 256;
    const int pool_grid   = (N_NODES * 32 + 255) / 256;

    // Layer 1
    k_gemm<false, false><<<gemm_grid, 256>>>(x, W1, nullptr);
    k_gather<<<gather_grid, 256>>>();

    // Layer 2: A = relu(agg1 + b1) fused into A-load (reads g_bufA, writes g_bufH)
    k_gemm<true, true><<<gemm_grid, 256>>>(nullptr, W2, b1);
    k_gather<<<gather_grid, 256>>>();

    // relu(agg2+b2), FC dot, segment mean
    k_pool<<<pool_grid, 256>>>(b2, Wfc, batch);
    k_final<<<1, 256>>>(out, bfc);
}

// round 10
// speedup vs baseline: 1.5745x; 1.0476x over previous
#include <cuda_runtime.h>
#include <cstdint>

#define N_NODES  100000
#define N_EDGES  1600000
#define CH       128
#define N_GRAPHS 256

#define SCAN_BLK 512
#define N_SCAN_BLKS ((N_NODES + SCAN_BLK - 1) / SCAN_BLK)   // 196

// ---------------- scratch (device globals; no allocation allowed) ----------
__device__ float g_bufH[(size_t)N_NODES * CH];   // h (GEMM output, gather source)
__device__ float g_bufA[(size_t)N_NODES * CH];   // agg (gather output / next GEMM input)
__device__ int   g_degcnt[N_NODES];              // in-degree (no self loop)
__device__ int   g_rowstart[N_NODES];            // CSR row starts (exclusive scan of degcnt)
__device__ int   g_rowcur[N_NODES];              // placement cursors
__device__ int   g_blksum[N_SCAN_BLKS];          // scan block sums
__device__ int2  g_edge[N_EDGES];                // CSR: {src, coef-as-int-bits} per dst-sorted edge
__device__ float g_dinv[N_NODES];                // 1/deg
__device__ float g_dis[N_NODES];                 // deg^-0.5
__device__ float g_psum[N_GRAPHS];
__device__ float g_cnt[N_GRAPHS];

// ---------------- setup -----------------------------------------------------
__global__ void k_zero() {
    int i = blockIdx.x * blockDim.x + threadIdx.x;
    if (i < N_NODES) { g_degcnt[i] = 0; g_rowcur[i] = 0; }
    if (i < N_GRAPHS) { g_psum[i] = 0.f; g_cnt[i] = 0.f; }
}

__global__ void k_degcount(const int* __restrict__ dst) {
    int e = blockIdx.x * blockDim.x + threadIdx.x;
    if (e < N_EDGES) atomicAdd(&g_degcnt[dst[e]], 1);
}

// ---------------- CSR build: 3-pass exclusive scan + placement fill ---------
__global__ void __launch_bounds__(SCAN_BLK) k_scan1() {
    __shared__ int sc[SCAN_BLK];
    int t = threadIdx.x;
    int i = blockIdx.x * SCAN_BLK + t;
    int v = (i < N_NODES) ? g_degcnt[i] : 0;
    sc[t] = v;
    __syncthreads();
    #pragma unroll
    for (int o = 1; o < SCAN_BLK; o <<= 1) {
        int u = (t >= o) ? sc[t - o] : 0;
        __syncthreads();
        sc[t] += u;
        __syncthreads();
    }
    if (i < N_NODES) g_rowstart[i] = sc[t] - v;      // exclusive within block
    if (t == SCAN_BLK - 1) g_blksum[blockIdx.x] = sc[t];
}

__global__ void __launch_bounds__(256) k_scan2() {
    __shared__ int sc[256];
    int t = threadIdx.x;
    int v = (t < N_SCAN_BLKS) ? g_blksum[t] : 0;
    sc[t] = v;
    __syncthreads();
    #pragma unroll
    for (int o = 1; o < 256; o <<= 1) {
        int u = (t >= o) ? sc[t - o] : 0;
        __syncthreads();
        sc[t] += u;
        __syncthreads();
    }
    if (t < N_SCAN_BLKS) g_blksum[t] = sc[t] - v;    // exclusive block offsets
}

// scan finalize + degree normalization terms (merged kernel)
__global__ void k_scan3() {
    int i = blockIdx.x * blockDim.x + threadIdx.x;
    if (i < N_NODES) {
        g_rowstart[i] += g_blksum[i / SCAN_BLK];
        float deg = 1.f + (float)g_degcnt[i];
        g_dinv[i] = 1.f / deg;
        g_dis[i]  = rsqrtf(deg);
    }
}

__global__ void __launch_bounds__(256)
k_fill(const int* __restrict__ src, const int* __restrict__ dst) {
    int e = blockIdx.x * blockDim.x + threadIdx.x;
    if (e >= N_EDGES) return;
    int s = __ldg(src + e);
    int d = __ldg(dst + e);
    int pos = g_rowstart[d] + atomicAdd(&g_rowcur[d], 1);
    float coef = g_dis[s] * g_dis[d];
    g_edge[pos] = make_int2(s, __float_as_int(coef));
}

// ---------------- tiled SGEMM: [M,128] @ [128,128], 128x128 block tile ------
// 256 threads, 8x8 per-thread micro-tile, A transposed in smem.
// Per kk-step: 4 LDS.128 feed 64 FMA. Epilogue writes H only.
template<bool RELU_BIAS, bool X_FROM_AGG>
__global__ void __launch_bounds__(256)
k_gemm(const float* __restrict__ Xext, const float* __restrict__ W,
       const float* __restrict__ bias)
{
    __shared__ float As[16][132];   // [k][m], padded
    __shared__ float Ws[16][128];   // [k][n]

    const float* __restrict__ X = X_FROM_AGG ? (const float*)g_bufA : Xext;

    const int tx   = threadIdx.x;
    const int row0 = blockIdx.x * 128;
    const int lrow = tx >> 2;          // A-load row 0..63 (and +64)
    const int lk4  = (tx & 3) * 4;     // A-load k offset 0,4,8,12
    const int cx   = tx & 15;          // col block: cols cx*8 .. cx*8+7
    const int ry   = tx >> 4;          // row block: rows ry*8 .. ry*8+7

    float acc[8][8];
    #pragma unroll
    for (int i = 0; i < 8; i++)
        #pragma unroll
        for (int j = 0; j < 8; j++) acc[i][j] = 0.f;

    for (int kt = 0; kt < CH; kt += 16) {
        // A tile: 128 rows x 16 k, transposed store
        #pragma unroll
        for (int h = 0; h < 2; h++) {
            int r = row0 + lrow + h * 64;
            float4 av = make_float4(0.f, 0.f, 0.f, 0.f);
            if (r < N_NODES) {
                av = *(const float4*)(X + (size_t)r * CH + kt + lk4);
                if (RELU_BIAS) {
                    av.x = fmaxf(av.x + bias[kt + lk4 + 0], 0.f);
                    av.y = fmaxf(av.y + bias[kt + lk4 + 1], 0.f);
                    av.z = fmaxf(av.z + bias[kt + lk4 + 2], 0.f);
                    av.w = fmaxf(av.w + bias[kt + lk4 + 3], 0.f);
                }
            }
            As[lk4 + 0][lrow + h * 64] = av.x;
            As[lk4 + 1][lrow + h * 64] = av.y;
            As[lk4 + 2][lrow + h * 64] = av.z;
            As[lk4 + 3][lrow + h * 64] = av.w;
        }
        // W tile: 16 x 128 (512 float4 / 256 threads)
        #pragma unroll
        for (int h = 0; h < 2; h++) {
            int idx = tx + h * 256;
            int kk = idx >> 5, c4 = idx & 31;
            *(float4*)&Ws[kk][c4 * 4] = ((const float4*)W)[(size_t)(kt + kk) * 32 + c4];
        }
        __syncthreads();

        #pragma unroll
        for (int kk = 0; kk < 16; kk++) {
            float a[8], b[8];
            *(float4*)&a[0] = *(const float4*)&As[kk][ry * 8];
            *(float4*)&a[4] = *(const float4*)&As[kk][ry * 8 + 4];
            *(float4*)&b[0] = *(const float4*)&Ws[kk][cx * 8];
            *(float4*)&b[4] = *(const float4*)&Ws[kk][cx * 8 + 4];
            #pragma unroll
            for (int i = 0; i < 8; i++)
                #pragma unroll
                for (int j = 0; j < 8; j++)
                    acc[i][j] = fmaf(a[i], b[j], acc[i][j]);
        }
        __syncthreads();
    }

    #pragma unroll
    for (int i = 0; i < 8; i++) {
        int r = row0 + ry * 8 + i;
        if (r < N_NODES) {
            *(float4*)(g_bufH + (size_t)r * CH + cx * 8) =
                make_float4(acc[i][0], acc[i][1], acc[i][2], acc[i][3]);
            *(float4*)(g_bufH + (size_t)r * CH + cx * 8 + 4) =
                make_float4(acc[i][4], acc[i][5], acc[i][6], acc[i][7]);
        }
    }
}

// ---------------- CSR gather: Agg[n] = H[n]/deg + sum_e coef*H[src] ---------
// Warp per node; register accumulation; one plain store. NO atomics.
// Inner loop unrolled x4 with NO tail logic: lanes >= m hold ec = {0, 0.0f},
// so out-of-range steps gather row 0 scaled by 0 (harmless, L2-cached).
__global__ void __launch_bounds__(256)
k_gather()
{
    int gt = blockIdx.x * blockDim.x + threadIdx.x;
    int n = gt >> 5;
    if (n >= N_NODES) return;
    int lane = gt & 31;

    int beg = g_rowstart[n];
    int cnt = g_degcnt[n];
    float di = g_dinv[n];

    float4 h = *(const float4*)(g_bufH + (size_t)n * CH + lane * 4);
    float4 acc = make_float4(h.x * di, h.y * di, h.z * di, h.w * di);

    for (int base = 0; base < cnt; base += 32) {
        int rem = cnt - base;
        int m = rem < 32 ? rem : 32;
        int2 ec = make_int2(0, 0);
        if (lane < m) ec = __ldg(g_edge + beg + base + lane);

        for (int j = 0; j < m; j += 4) {
            int   s0 = __shfl_sync(0xFFFFFFFFu, ec.x, j);
            int   s1 = __shfl_sync(0xFFFFFFFFu, ec.x, j + 1);
            int   s2 = __shfl_sync(0xFFFFFFFFu, ec.x, j + 2);
            int   s3 = __shfl_sync(0xFFFFFFFFu, ec.x, j + 3);
            float c0 = __int_as_float(__shfl_sync(0xFFFFFFFFu, ec.y, j));
            float c1 = __int_as_float(__shfl_sync(0xFFFFFFFFu, ec.y, j + 1));
            float c2 = __int_as_float(__shfl_sync(0xFFFFFFFFu, ec.y, j + 2));
            float c3 = __int_as_float(__shfl_sync(0xFFFFFFFFu, ec.y, j + 3));
            float4 v0 = *(const float4*)(g_bufH + (size_t)s0 * CH + lane * 4);
            float4 v1 = *(const float4*)(g_bufH + (size_t)s1 * CH + lane * 4);
            float4 v2 = *(const float4*)(g_bufH + (size_t)s2 * CH + lane * 4);
            float4 v3 = *(const float4*)(g_bufH + (size_t)s3 * CH + lane * 4);
            acc.x = fmaf(c0, v0.x, fmaf(c1, v1.x, fmaf(c2, v2.x, fmaf(c3, v3.x, acc.x))));
            acc.y = fmaf(c0, v0.y, fmaf(c1, v1.y, fmaf(c2, v2.y, fmaf(c3, v3.y, acc.y))));
            acc.z = fmaf(c0, v0.z, fmaf(c1, v1.z, fmaf(c2, v2.z, fmaf(c3, v3.z, acc.z))));
            acc.w = fmaf(c0, v0.w, fmaf(c1, v1.w, fmaf(c2, v2.w, fmaf(c3, v3.w, acc.w))));
        }
    }

    *(float4*)(g_bufA + (size_t)n * CH + lane * 4) = acc;
}

// ---------------- fused relu(+b2) + FC dot + segment mean accumulation ------
__global__ void __launch_bounds__(256)
k_pool(const float* __restrict__ b2,
       const float* __restrict__ Wfc, const int* __restrict__ batch)
{
    int gtid = blockIdx.x * blockDim.x + threadIdx.x;
    int n = gtid >> 5;
    if (n >= N_NODES) return;
    int lane = gtid & 31;
    float4 h = *(const float4*)(g_bufA + (size_t)n * CH + lane * 4);
    float4 bb = ((const float4*)b2)[lane];
    float4 w  = ((const float4*)Wfc)[lane];
    float s = fmaxf(h.x + bb.x, 0.f) * w.x
            + fmaxf(h.y + bb.y, 0.f) * w.y
            + fmaxf(h.z + bb.z, 0.f) * w.z
            + fmaxf(h.w + bb.w, 0.f) * w.w;
    #pragma unroll
    for (int off = 16; off; off >>= 1)
        s += __shfl_xor_sync(0xFFFFFFFFu, s, off);
    if (lane == 0) {
        int g = __ldg(batch + n);
        atomicAdd(&g_psum[g], s);
        atomicAdd(&g_cnt[g], 1.f);
    }
}

__global__ void k_final(float* __restrict__ out, const float* __restrict__ bfc) {
    int g = threadIdx.x;
    if (g < N_GRAPHS) out[g] = g_psum[g] / fmaxf(g_cnt[g], 1.f) + bfc[0];
}

// ---------------- launch -----------------------------------------------------
extern "C" void kernel_launch(void* const* d_in, const int* in_sizes, int n_in,
                              void* d_out, int out_size)
{
    (void)in_sizes; (void)n_in; (void)out_size;
    const float* x     = (const float*)d_in[0];
    const int*   ei    = (const int*)d_in[1];   // [2, E] row-major
    const int*   batch = (const int*)d_in[2];
    const float* W1    = (const float*)d_in[3];
    const float* b1    = (const float*)d_in[4];
    const float* W2    = (const float*)d_in[5];
    const float* b2    = (const float*)d_in[6];
    const float* Wfc   = (const float*)d_in[7];
    const float* bfc   = (const float*)d_in[8];
    float* out = (float*)d_out;

    const int* src = ei;            // edge_index[0]
    const int* dst = ei + N_EDGES;  // edge_index[1]

    // degree + CSR build
    k_zero<<<(N_NODES + 255) / 256, 256>>>();
    k_degcount<<<(N_EDGES + 255) / 256, 256>>>(dst);
    k_scan1<<<N_SCAN_BLKS, SCAN_BLK>>>();
    k_scan2<<<1, 256>>>();
    k_scan3<<<(N_NODES + 255) / 256, 256>>>();
    k_fill<<<(N_EDGES + 255) / 256, 256>>>(src, dst);

    const int gemm_grid   = (N_NODES + 127) / 128;
    const int gather_grid = (N_NODES * 32 + 255) / 256;
    const int pool_grid   = (N_NODES * 32 + 255) / 256;

    // Layer 1
    k_gemm<false, false><<<gemm_grid, 256>>>(x, W1, nullptr);
    k_gather<<<gather_grid, 256>>>();

    // Layer 2: A = relu(agg1 + b1) fused into A-load (reads g_bufA, writes g_bufH)
    k_gemm<true, true><<<gemm_grid, 256>>>(nullptr, W2, b1);
    k_gather<<<gather_grid, 256>>>();

    // relu(agg2+b2), FC dot, segment mean
    k_pool<<<pool_grid, 256>>>(b2, Wfc, batch);
    k_final<<<1, 256>>>(out, bfc);
}

// round 13
// speedup vs baseline: 1.8729x; 1.1895x over previous
#include <cuda_runtime.h>
#include <cstdint>

#define N_NODES  100000
#define N_EDGES  1600000
#define CH       128
#define N_GRAPHS 256

#define SCAN_BLK 512
#define N_SCAN_BLKS ((N_NODES + SCAN_BLK - 1) / SCAN_BLK)   // 196

// ---------------- scratch (device globals; no allocation allowed) ----------
__device__ float g_bufH[(size_t)N_NODES * CH];   // h (GEMM output, gather source)
__device__ float g_bufA[(size_t)N_NODES * CH];   // agg (gather output / next GEMM input)
__device__ int   g_degcnt[N_NODES];              // in-degree (no self loop)
__device__ int   g_rowstart[N_NODES];            // CSR row starts
__device__ int   g_rowcur[N_NODES];              // placement cursors
__device__ int   g_blksum[N_SCAN_BLKS];          // scan block sums
__device__ int2  g_edge[N_EDGES];                // CSR: {src, coef bits}
__device__ float g_dinv[N_NODES];                // 1/deg
__device__ float g_dis[N_NODES];                 // deg^-0.5
__device__ float g_psum[N_GRAPHS];
__device__ float g_cnt[N_GRAPHS];

// ---------------- setup -----------------------------------------------------
__global__ void k_zero() {
    int i = blockIdx.x * blockDim.x + threadIdx.x;
    if (i < N_NODES) { g_degcnt[i] = 0; g_rowcur[i] = 0; }
    if (i < N_GRAPHS) { g_psum[i] = 0.f; g_cnt[i] = 0.f; }
}

__global__ void k_degcount(const int* __restrict__ dst) {
    int e = blockIdx.x * blockDim.x + threadIdx.x;
    if (e < N_EDGES) atomicAdd(&g_degcnt[dst[e]], 1);
}

// ---------------- CSR build: 3-pass exclusive scan + placement fill ---------
__global__ void __launch_bounds__(SCAN_BLK) k_scan1() {
    __shared__ int sc[SCAN_BLK];
    int t = threadIdx.x;
    int i = blockIdx.x * SCAN_BLK + t;
    int v = (i < N_NODES) ? g_degcnt[i] : 0;
    sc[t] = v;
    __syncthreads();
    #pragma unroll
    for (int o = 1; o < SCAN_BLK; o <<= 1) {
        int u = (t >= o) ? sc[t - o] : 0;
        __syncthreads();
        sc[t] += u;
        __syncthreads();
    }
    if (i < N_NODES) g_rowstart[i] = sc[t] - v;
    if (t == SCAN_BLK - 1) g_blksum[blockIdx.x] = sc[t];
}

__global__ void __launch_bounds__(256) k_scan2() {
    __shared__ int sc[256];
    int t = threadIdx.x;
    int v = (t < N_SCAN_BLKS) ? g_blksum[t] : 0;
    sc[t] = v;
    __syncthreads();
    #pragma unroll
    for (int o = 1; o < 256; o <<= 1) {
        int u = (t >= o) ? sc[t - o] : 0;
        __syncthreads();
        sc[t] += u;
        __syncthreads();
    }
    if (t < N_SCAN_BLKS) g_blksum[t] = sc[t] - v;
}

// scan finalize + degree normalization terms (merged kernel)
__global__ void k_scan3() {
    int i = blockIdx.x * blockDim.x + threadIdx.x;
    if (i < N_NODES) {
        g_rowstart[i] += g_blksum[i / SCAN_BLK];
        float deg = 1.f + (float)g_degcnt[i];
        g_dinv[i] = 1.f / deg;
        g_dis[i]  = rsqrtf(deg);
    }
}

__global__ void __launch_bounds__(256)
k_fill(const int* __restrict__ src, const int* __restrict__ dst) {
    int e = blockIdx.x * blockDim.x + threadIdx.x;
    if (e >= N_EDGES) return;
    int s = __ldg(src + e);
    int d = __ldg(dst + e);
    int pos = g_rowstart[d] + atomicAdd(&g_rowcur[d], 1);
    float coef = g_dis[s] * g_dis[d];
    g_edge[pos] = make_int2(s, __float_as_int(coef));
}

// ---------------- TF32 tensor-core GEMM: [M,128] @ [128,128] ----------------
// Block 128x128 tile, 8 warps (4 m x 2 n). Warp tile 32x64.
// mma.sync m16n8k8 tf32, fp32 accumulate. Fragments loaded straight from
// gmem (A rows + 64KB W are 32B-sector aligned per quad; W is L1-resident).
__device__ __forceinline__ uint32_t tf32r(float x) {
    uint32_t u;
    asm("cvt.rna.tf32.f32 %0, %1;" : "=r"(u) : "f"(x));
    return u;
}

__device__ __forceinline__ void mma_tf32(float* d, const uint32_t* a,
                                         uint32_t b0, uint32_t b1) {
    asm volatile(
        "mma.sync.aligned.m16n8k8.row.col.f32.tf32.tf32.f32 "
        "{%0,%1,%2,%3}, {%4,%5,%6,%7}, {%8,%9}, {%0,%1,%2,%3};"
        : "+f"(d[0]), "+f"(d[1]), "+f"(d[2]), "+f"(d[3])
        : "r"(a[0]), "r"(a[1]), "r"(a[2]), "r"(a[3]), "r"(b0), "r"(b1));
}

template<bool RELU_BIAS, bool X_FROM_AGG>
__global__ void __launch_bounds__(256)
k_gemm(const float* __restrict__ Xext, const float* __restrict__ W,
       const float* __restrict__ bias)
{
    const float* __restrict__ X = X_FROM_AGG ? (const float*)g_bufA : Xext;

    const int tx     = threadIdx.x;
    const int wid    = tx >> 5;
    const int lane   = tx & 31;
    const int grp    = lane >> 2;      // 0..7
    const int tig    = lane & 3;       // 0..3
    const int warp_m = wid & 3;        // 4 warps along M
    const int warp_n = wid >> 2;       // 2 warps along N
    const int row0   = blockIdx.x * 128 + warp_m * 32;
    const int col0   = warp_n * 64;

    // clamped row pointers for the two m-tiles (rows fixed per thread)
    const float* pr[2][2];
    int rr[2][2];
    #pragma unroll
    for (int mt = 0; mt < 2; mt++) {
        int r0 = row0 + mt * 16 + grp;
        int r1 = r0 + 8;
        rr[mt][0] = r0; rr[mt][1] = r1;
        int rc0 = r0 < N_NODES ? r0 : N_NODES - 1;
        int rc1 = r1 < N_NODES ? r1 : N_NODES - 1;
        pr[mt][0] = X + (size_t)rc0 * CH;
        pr[mt][1] = X + (size_t)rc1 * CH;
    }

    float acc[2][8][4];
    #pragma unroll
    for (int mt = 0; mt < 2; mt++)
        #pragma unroll
        for (int nt = 0; nt < 8; nt++)
            #pragma unroll
            for (int q = 0; q < 4; q++) acc[mt][nt][q] = 0.f;

    #pragma unroll 2
    for (int k = 0; k < CH; k += 8) {
        float bb0 = 0.f, bb1 = 0.f;
        if (RELU_BIAS) {
            bb0 = __ldg(bias + k + tig);
            bb1 = __ldg(bias + k + tig + 4);
        }
        uint32_t afr[2][4];
        #pragma unroll
        for (int mt = 0; mt < 2; mt++) {
            float a0 = __ldg(pr[mt][0] + k + tig);
            float a1 = __ldg(pr[mt][1] + k + tig);
            float a2 = __ldg(pr[mt][0] + k + tig + 4);
            float a3 = __ldg(pr[mt][1] + k + tig + 4);
            if (RELU_BIAS) {
                a0 = fmaxf(a0 + bb0, 0.f);
                a1 = fmaxf(a1 + bb0, 0.f);
                a2 = fmaxf(a2 + bb1, 0.f);
                a3 = fmaxf(a3 + bb1, 0.f);
            }
            afr[mt][0] = tf32r(a0); afr[mt][1] = tf32r(a1);
            afr[mt][2] = tf32r(a2); afr[mt][3] = tf32r(a3);
        }
        #pragma unroll
        for (int nt = 0; nt < 8; nt++) {
            int c = col0 + nt * 8 + grp;
            uint32_t b0 = tf32r(__ldg(W + (size_t)(k + tig) * CH + c));
            uint32_t b1 = tf32r(__ldg(W + (size_t)(k + tig + 4) * CH + c));
            mma_tf32(acc[0][nt], afr[0], b0, b1);
            mma_tf32(acc[1][nt], afr[1], b0, b1);
        }
    }

    // store D: row = rr[mt][h], col = col0 + nt*8 + 2*tig (float2 pairs)
    #pragma unroll
    for (int mt = 0; mt < 2; mt++)
        #pragma unroll
        for (int h = 0; h < 2; h++) {
            int r = rr[mt][h];
            if (r < N_NODES) {
                float* dst = g_bufH + (size_t)r * CH;
                #pragma unroll
                for (int nt = 0; nt < 8; nt++) {
                    int c = col0 + nt * 8 + 2 * tig;
                    *(float2*)(dst + c) =
                        make_float2(acc[mt][nt][h * 2], acc[mt][nt][h * 2 + 1]);
                }
            }
        }
}

// ---------------- CSR gather: Agg[n] = H[n]/deg + sum_e coef*H[src] ---------
// Warp per node; register accumulation; NO atomics on features.
// FINAL: fuse relu(+b2) + FC dot + segment-mean accumulation (skip bufA write).
template<bool FINAL>
__global__ void __launch_bounds__(256)
k_gather(const float* __restrict__ b2, const float* __restrict__ Wfc,
         const int* __restrict__ batch)
{
    int gt = blockIdx.x * blockDim.x + threadIdx.x;
    int n = gt >> 5;
    if (n >= N_NODES) return;
    int lane = gt & 31;

    int beg = g_rowstart[n];
    int cnt = g_degcnt[n];
    float di = g_dinv[n];

    float4 h = *(const float4*)(g_bufH + (size_t)n * CH + lane * 4);
    float4 acc = make_float4(h.x * di, h.y * di, h.z * di, h.w * di);

    for (int base = 0; base < cnt; base += 32) {
        int rem = cnt - base;
        int m = rem < 32 ? rem : 32;
        int2 ec = make_int2(0, 0);
        if (lane < m) ec = __ldg(g_edge + beg + base + lane);

        for (int j = 0; j < m; j += 4) {
            int   s0 = __shfl_sync(0xFFFFFFFFu, ec.x, j);
            int   s1 = __shfl_sync(0xFFFFFFFFu, ec.x, j + 1);
            int   s2 = __shfl_sync(0xFFFFFFFFu, ec.x, j + 2);
            int   s3 = __shfl_sync(0xFFFFFFFFu, ec.x, j + 3);
            float c0 = __int_as_float(__shfl_sync(0xFFFFFFFFu, ec.y, j));
            float c1 = __int_as_float(__shfl_sync(0xFFFFFFFFu, ec.y, j + 1));
            float c2 = __int_as_float(__shfl_sync(0xFFFFFFFFu, ec.y, j + 2));
            float c3 = __int_as_float(__shfl_sync(0xFFFFFFFFu, ec.y, j + 3));
            float4 v0 = *(const float4*)(g_bufH + (size_t)s0 * CH + lane * 4);
            float4 v1 = *(const float4*)(g_bufH + (size_t)s1 * CH + lane * 4);
            float4 v2 = *(const float4*)(g_bufH + (size_t)s2 * CH + lane * 4);
            float4 v3 = *(const float4*)(g_bufH + (size_t)s3 * CH + lane * 4);
            acc.x = fmaf(c0, v0.x, fmaf(c1, v1.x, fmaf(c2, v2.x, fmaf(c3, v3.x, acc.x))));
            acc.y = fmaf(c0, v0.y, fmaf(c1, v1.y, fmaf(c2, v2.y, fmaf(c3, v3.y, acc.y))));
            acc.z = fmaf(c0, v0.z, fmaf(c1, v1.z, fmaf(c2, v2.z, fmaf(c3, v3.z, acc.z))));
            acc.w = fmaf(c0, v0.w, fmaf(c1, v1.w, fmaf(c2, v2.w, fmaf(c3, v3.w, acc.w))));
        }
    }

    if (!FINAL) {
        *(float4*)(g_bufA + (size_t)n * CH + lane * 4) = acc;
    } else {
        float4 bb = ((const float4*)b2)[lane];
        float4 w  = ((const float4*)Wfc)[lane];
        float s = fmaxf(acc.x + bb.x, 0.f) * w.x
                + fmaxf(acc.y + bb.y, 0.f) * w.y
                + fmaxf(acc.z + bb.z, 0.f) * w.z
                + fmaxf(acc.w + bb.w, 0.f) * w.w;
        #pragma unroll
        for (int off = 16; off; off >>= 1)
            s += __shfl_xor_sync(0xFFFFFFFFu, s, off);
        if (lane == 0) {
            int g = __ldg(batch + n);
            atomicAdd(&g_psum[g], s);
            atomicAdd(&g_cnt[g], 1.f);
        }
    }
}

__global__ void k_final(float* __restrict__ out, const float* __restrict__ bfc) {
    int g = threadIdx.x;
    if (g < N_GRAPHS) out[g] = g_psum[g] / fmaxf(g_cnt[g], 1.f) + bfc[0];
}

// ---------------- launch -----------------------------------------------------
extern "C" void kernel_launch(void* const* d_in, const int* in_sizes, int n_in,
                              void* d_out, int out_size)
{
    (void)in_sizes; (void)n_in; (void)out_size;
    const float* x     = (const float*)d_in[0];
    const int*   ei    = (const int*)d_in[1];   // [2, E] row-major
    const int*   batch = (const int*)d_in[2];
    const float* W1    = (const float*)d_in[3];
    const float* b1    = (const float*)d_in[4];
    const float* W2    = (const float*)d_in[5];
    const float* b2    = (const float*)d_in[6];
    const float* Wfc   = (const float*)d_in[7];
    const float* bfc   = (const float*)d_in[8];
    float* out = (float*)d_out;

    const int* src = ei;            // edge_index[0]
    const int* dst = ei + N_EDGES;  // edge_index[1]

    // degree + CSR build
    k_zero<<<(N_NODES + 255) / 256, 256>>>();
    k_degcount<<<(N_EDGES + 255) / 256, 256>>>(dst);
    k_scan1<<<N_SCAN_BLKS, SCAN_BLK>>>();
    k_scan2<<<1, 256>>>();
    k_scan3<<<(N_NODES + 255) / 256, 256>>>();
    k_fill<<<(N_EDGES + 255) / 256, 256>>>(src, dst);

    const int gemm_grid   = (N_NODES + 127) / 128;
    const int gather_grid = (N_NODES * 32 + 255) / 256;

    // Layer 1
    k_gemm<false, false><<<gemm_grid, 256>>>(x, W1, nullptr);
    k_gather<false><<<gather_grid, 256>>>(nullptr, nullptr, nullptr);

    // Layer 2: A = relu(agg1 + b1) fused into A fragments (reads g_bufA)
    k_gemm<true, true><<<gemm_grid, 256>>>(nullptr, W2, b1);
    // gather 2 fused with relu(+b2) + FC dot + segment mean
    k_gather<true><<<gather_grid, 256>>>(b2, Wfc, batch);

    k_final<<<1, 256>>>(out, bfc);
}

// round 15
// speedup vs baseline: 1.9527x; 1.0426x over previous
#include <cuda_runtime.h>
#include <cuda_fp16.h>
#include <cstdint>

#define N_NODES  100000
#define N_EDGES  1600000
#define CH       128
#define N_GRAPHS 256

#define SCAN_BLK 512
#define N_SCAN_BLKS ((N_NODES + SCAN_BLK - 1) / SCAN_BLK)   // 196

// ---------------- scratch (device globals; no allocation allowed) ----------
__device__ __half g_bufH[(size_t)N_NODES * CH]; // h (GEMM out, fp16, gather src)
__device__ float  g_bufA[(size_t)N_NODES * CH]; // agg (gather out / GEMM2 input)
__device__ int   g_degcnt[N_NODES];             // in-degree (no self loop)
__device__ int   g_rowstart[N_NODES];           // CSR row starts
__device__ int   g_rowcur[N_NODES];             // placement cursors
__device__ int   g_blksum[N_SCAN_BLKS];         // scan block sums
__device__ int2  g_edge[N_EDGES];               // CSR: {src, coef bits}
__device__ float g_dinv[N_NODES];               // 1/deg
__device__ float g_dis[N_NODES];                // deg^-0.5
__device__ float g_psum[N_GRAPHS];
__device__ float g_cnt[N_GRAPHS];

// ---------------- setup -----------------------------------------------------
__global__ void k_zero() {
    int i = blockIdx.x * blockDim.x + threadIdx.x;
    if (i < N_NODES) { g_degcnt[i] = 0; g_rowcur[i] = 0; }
    if (i < N_GRAPHS) { g_psum[i] = 0.f; g_cnt[i] = 0.f; }
}

__global__ void k_degcount(const int* __restrict__ dst) {
    int e = blockIdx.x * blockDim.x + threadIdx.x;
    if (e < N_EDGES) atomicAdd(&g_degcnt[dst[e]], 1);
}

// ---------------- CSR build: 3-pass exclusive scan + placement fill ---------
__global__ void __launch_bounds__(SCAN_BLK) k_scan1() {
    __shared__ int sc[SCAN_BLK];
    int t = threadIdx.x;
    int i = blockIdx.x * SCAN_BLK + t;
    int v = (i < N_NODES) ? g_degcnt[i] : 0;
    sc[t] = v;
    __syncthreads();
    #pragma unroll
    for (int o = 1; o < SCAN_BLK; o <<= 1) {
        int u = (t >= o) ? sc[t - o] : 0;
        __syncthreads();
        sc[t] += u;
        __syncthreads();
    }
    if (i < N_NODES) g_rowstart[i] = sc[t] - v;
    if (t == SCAN_BLK - 1) g_blksum[blockIdx.x] = sc[t];
}

__global__ void __launch_bounds__(256) k_scan2() {
    __shared__ int sc[256];
    int t = threadIdx.x;
    int v = (t < N_SCAN_BLKS) ? g_blksum[t] : 0;
    sc[t] = v;
    __syncthreads();
    #pragma unroll
    for (int o = 1; o < 256; o <<= 1) {
        int u = (t >= o) ? sc[t - o] : 0;
        __syncthreads();
        sc[t] += u;
        __syncthreads();
    }
    if (t < N_SCAN_BLKS) g_blksum[t] = sc[t] - v;
}

// scan finalize + degree normalization terms (merged kernel)
__global__ void k_scan3() {
    int i = blockIdx.x * blockDim.x + threadIdx.x;
    if (i < N_NODES) {
        g_rowstart[i] += g_blksum[i / SCAN_BLK];
        float deg = 1.f + (float)g_degcnt[i];
        g_dinv[i] = 1.f / deg;
        g_dis[i]  = rsqrtf(deg);
    }
}

__global__ void __launch_bounds__(256)
k_fill(const int* __restrict__ src, const int* __restrict__ dst) {
    int e = blockIdx.x * blockDim.x + threadIdx.x;
    if (e >= N_EDGES) return;
    int s = __ldg(src + e);
    int d = __ldg(dst + e);
    int pos = g_rowstart[d] + atomicAdd(&g_rowcur[d], 1);
    float coef = g_dis[s] * g_dis[d];
    g_edge[pos] = make_int2(s, __float_as_int(coef));
}

// ---------------- TF32 tensor-core GEMM: [M,128] @ [128,128] ----------------
// Block 128x128 tile, 8 warps (4 m x 2 n). Warp tile 32x64.
// mma.sync m16n8k8 tf32, fp32 accumulate. Epilogue stores H as fp16 (half2).
__device__ __forceinline__ uint32_t tf32r(float x) {
    uint32_t u;
    asm("cvt.rna.tf32.f32 %0, %1;" : "=r"(u) : "f"(x));
    return u;
}

__device__ __forceinline__ void mma_tf32(float* d, const uint32_t* a,
                                         uint32_t b0, uint32_t b1) {
    asm volatile(
        "mma.sync.aligned.m16n8k8.row.col.f32.tf32.tf32.f32 "
        "{%0,%1,%2,%3}, {%4,%5,%6,%7}, {%8,%9}, {%0,%1,%2,%3};"
        : "+f"(d[0]), "+f"(d[1]), "+f"(d[2]), "+f"(d[3])
        : "r"(a[0]), "r"(a[1]), "r"(a[2]), "r"(a[3]), "r"(b0), "r"(b1));
}

template<bool RELU_BIAS, bool X_FROM_AGG>
__global__ void __launch_bounds__(256)
k_gemm(const float* __restrict__ Xext, const float* __restrict__ W,
       const float* __restrict__ bias)
{
    const float* __restrict__ X = X_FROM_AGG ? (const float*)g_bufA : Xext;

    const int tx     = threadIdx.x;
    const int wid    = tx >> 5;
    const int lane   = tx & 31;
    const int grp    = lane >> 2;      // 0..7
    const int tig    = lane & 3;       // 0..3
    const int warp_m = wid & 3;        // 4 warps along M
    const int warp_n = wid >> 2;       // 2 warps along N
    const int row0   = blockIdx.x * 128 + warp_m * 32;
    const int col0   = warp_n * 64;

    // clamped row pointers for the two m-tiles (rows fixed per thread)
    const float* pr[2][2];
    int rr[2][2];
    #pragma unroll
    for (int mt = 0; mt < 2; mt++) {
        int r0 = row0 + mt * 16 + grp;
        int r1 = r0 + 8;
        rr[mt][0] = r0; rr[mt][1] = r1;
        int rc0 = r0 < N_NODES ? r0 : N_NODES - 1;
        int rc1 = r1 < N_NODES ? r1 : N_NODES - 1;
        pr[mt][0] = X + (size_t)rc0 * CH;
        pr[mt][1] = X + (size_t)rc1 * CH;
    }

    float acc[2][8][4];
    #pragma unroll
    for (int mt = 0; mt < 2; mt++)
        #pragma unroll
        for (int nt = 0; nt < 8; nt++)
            #pragma unroll
            for (int q = 0; q < 4; q++) acc[mt][nt][q] = 0.f;

    #pragma unroll 2
    for (int k = 0; k < CH; k += 8) {
        float bb0 = 0.f, bb1 = 0.f;
        if (RELU_BIAS) {
            bb0 = __ldg(bias + k + tig);
            bb1 = __ldg(bias + k + tig + 4);
        }
        uint32_t afr[2][4];
        #pragma unroll
        for (int mt = 0; mt < 2; mt++) {
            float a0 = __ldg(pr[mt][0] + k + tig);
            float a1 = __ldg(pr[mt][1] + k + tig);
            float a2 = __ldg(pr[mt][0] + k + tig + 4);
            float a3 = __ldg(pr[mt][1] + k + tig + 4);
            if (RELU_BIAS) {
                a0 = fmaxf(a0 + bb0, 0.f);
                a1 = fmaxf(a1 + bb0, 0.f);
                a2 = fmaxf(a2 + bb1, 0.f);
                a3 = fmaxf(a3 + bb1, 0.f);
            }
            afr[mt][0] = tf32r(a0); afr[mt][1] = tf32r(a1);
            afr[mt][2] = tf32r(a2); afr[mt][3] = tf32r(a3);
        }
        #pragma unroll
        for (int nt = 0; nt < 8; nt++) {
            int c = col0 + nt * 8 + grp;
            uint32_t b0 = tf32r(__ldg(W + (size_t)(k + tig) * CH + c));
            uint32_t b1 = tf32r(__ldg(W + (size_t)(k + tig + 4) * CH + c));
            mma_tf32(acc[0][nt], afr[0], b0, b1);
            mma_tf32(acc[1][nt], afr[1], b0, b1);
        }
    }

    // store D as fp16: row = rr[mt][h], col = col0 + nt*8 + 2*tig (half2)
    #pragma unroll
    for (int mt = 0; mt < 2; mt++)
        #pragma unroll
        for (int h = 0; h < 2; h++) {
            int r = rr[mt][h];
            if (r < N_NODES) {
                __half* dst = g_bufH + (size_t)r * CH;
                #pragma unroll
                for (int nt = 0; nt < 8; nt++) {
                    int c = col0 + nt * 8 + 2 * tig;
                    __half2 hv = __floats2half2_rn(acc[mt][nt][h * 2],
                                                   acc[mt][nt][h * 2 + 1]);
                    *(__half2*)(dst + c) = hv;
                }
            }
        }
}

// ---------------- CSR gather: Agg[n] = H[n]/deg + sum_e coef*H[src] ---------
// Warp per node; H rows are fp16 (8B per lane), fp32 accumulation.
// FINAL: fuse relu(+b2) + FC dot + segment-mean accumulation (skip bufA write).
__device__ __forceinline__ void acc_row(float4& acc, float c, uint2 raw) {
    float2 lo = __half22float2(*(__half2*)&raw.x);
    float2 hi = __half22float2(*(__half2*)&raw.y);
    acc.x = fmaf(c, lo.x, acc.x);
    acc.y = fmaf(c, lo.y, acc.y);
    acc.z = fmaf(c, hi.x, acc.z);
    acc.w = fmaf(c, hi.y, acc.w);
}

template<bool FINAL>
__global__ void __launch_bounds__(256)
k_gather(const float* __restrict__ b2, const float* __restrict__ Wfc,
         const int* __restrict__ batch)
{
    int gt = blockIdx.x * blockDim.x + threadIdx.x;
    int n = gt >> 5;
    if (n >= N_NODES) return;
    int lane = gt & 31;

    int beg = g_rowstart[n];
    int cnt = g_degcnt[n];
    float di = g_dinv[n];

    // self-loop term
    uint2 hraw = __ldg((const uint2*)(g_bufH + (size_t)n * CH) + lane);
    float4 acc = make_float4(0.f, 0.f, 0.f, 0.f);
    acc_row(acc, di, hraw);

    for (int base = 0; base < cnt; base += 32) {
        int rem = cnt - base;
        int m = rem < 32 ? rem : 32;
        int2 ec = make_int2(0, 0);
        if (lane < m) ec = __ldg(g_edge + beg + base + lane);

        for (int j = 0; j < m; j += 4) {
            int   s0 = __shfl_sync(0xFFFFFFFFu, ec.x, j);
            int   s1 = __shfl_sync(0xFFFFFFFFu, ec.x, j + 1);
            int   s2 = __shfl_sync(0xFFFFFFFFu, ec.x, j + 2);
            int   s3 = __shfl_sync(0xFFFFFFFFu, ec.x, j + 3);
            float c0 = __int_as_float(__shfl_sync(0xFFFFFFFFu, ec.y, j));
            float c1 = __int_as_float(__shfl_sync(0xFFFFFFFFu, ec.y, j + 1));
            float c2 = __int_as_float(__shfl_sync(0xFFFFFFFFu, ec.y, j + 2));
            float c3 = __int_as_float(__shfl_sync(0xFFFFFFFFu, ec.y, j + 3));
            uint2 r0 = __ldg((const uint2*)(g_bufH + (size_t)s0 * CH) + lane);
            uint2 r1 = __ldg((const uint2*)(g_bufH + (size_t)s1 * CH) + lane);
            uint2 r2 = __ldg((const uint2*)(g_bufH + (size_t)s2 * CH) + lane);
            uint2 r3 = __ldg((const uint2*)(g_bufH + (size_t)s3 * CH) + lane);
            acc_row(acc, c0, r0);
            acc_row(acc, c1, r1);
            acc_row(acc, c2, r2);
            acc_row(acc, c3, r3);
        }
    }

    if (!FINAL) {
        *(float4*)(g_bufA + (size_t)n * CH + lane * 4) = acc;
    } else {
        float4 bb = ((const float4*)b2)[lane];
        float4 w  = ((const float4*)Wfc)[lane];
        float s = fmaxf(acc.x + bb.x, 0.f) * w.x
                + fmaxf(acc.y + bb.y, 0.f) * w.y
                + fmaxf(acc.z + bb.z, 0.f) * w.z
                + fmaxf(acc.w + bb.w, 0.f) * w.w;
        #pragma unroll
        for (int off = 16; off; off >>= 1)
            s += __shfl_xor_sync(0xFFFFFFFFu, s, off);
        if (lane == 0) {
            int g = __ldg(batch + n);
            atomicAdd(&g_psum[g], s);
            atomicAdd(&g_cnt[g], 1.f);
        }
    }
}

__global__ void k_final(float* __restrict__ out, const float* __restrict__ bfc) {
    int g = threadIdx.x;
    if (g < N_GRAPHS) out[g] = g_psum[g] / fmaxf(g_cnt[g], 1.f) + bfc[0];
}

// ---------------- launch -----------------------------------------------------
extern "C" void kernel_launch(void* const* d_in, const int* in_sizes, int n_in,
                              void* d_out, int out_size)
{
    (void)in_sizes; (void)n_in; (void)out_size;
    const float* x     = (const float*)d_in[0];
    const int*   ei    = (const int*)d_in[1];   // [2, E] row-major
    const int*   batch = (const int*)d_in[2];
    const float* W1    = (const float*)d_in[3];
    const float* b1    = (const float*)d_in[4];
    const float* W2    = (const float*)d_in[5];
    const float* b2    = (const float*)d_in[6];
    const float* Wfc   = (const float*)d_in[7];
    const float* bfc   = (const float*)d_in[8];
    float* out = (float*)d_out;

    const int* src = ei;            // edge_index[0]
    const int* dst = ei + N_EDGES;  // edge_index[1]

    // degree + CSR build
    k_zero<<<(N_NODES + 255) / 256, 256>>>();
    k_degcount<<<(N_EDGES + 255) / 256, 256>>>(dst);
    k_scan1<<<N_SCAN_BLKS, SCAN_BLK>>>();
    k_scan2<<<1, 256>>>();
    k_scan3<<<(N_NODES + 255) / 256, 256>>>();
    k_fill<<<(N_EDGES + 255) / 256, 256>>>(src, dst);

    const int gemm_grid   = (N_NODES + 127) / 128;
    const int gather_grid = (N_NODES * 32 + 255) / 256;

    // Layer 1
    k_gemm<false, false><<<gemm_grid, 256>>>(x, W1, nullptr);
    k_gather<false><<<gather_grid, 256>>>(nullptr, nullptr, nullptr);

    // Layer 2: A = relu(agg1 + b1) fused into A fragments (reads g_bufA)
    k_gemm<true, true><<<gemm_grid, 256>>>(nullptr, W2, b1);
    // gather 2 fused with relu(+b2) + FC dot + segment mean
    k_gather<true><<<gather_grid, 256>>>(b2, Wfc, batch);

    k_final<<<1, 256>>>(out, bfc);
}